// round 1
// baseline (speedup 1.0000x reference)
#include <cuda_runtime.h>
#include <math.h>

#define Bdim 4
#define Cdim 256
#define Ndim 2304      // 48*48
#define OUTC 256
#define PLANE (Bdim*Cdim*Ndim)   // 2359296 floats per [B,C,N] tensor

#define BM 128
#define BN 128
#define BK 16

// ---- scratch (device globals; allocation-free) ----
__device__ float g_P[9][PLANE];                       // Q0..Q2, K0..K2, V0..V2 (Q,K pre-scaled by s)
__device__ float g_S[(size_t)Bdim * Ndim * Ndim];     // scores, reused across the 3 attends
__device__ float g_W[3][PLANE];                       // attention outputs (rgb, depth, thermal)
__device__ float g_F[PLANE];                          // gated fused sum

// =====================================================================
// proj: dst[b][o][n] = scale * ( sum_c W[o][c] * X[b][c][n] + bias[o] )
// scale = s[s_idx] if s_idx>=0 else 1
// =====================================================================
__global__ void __launch_bounds__(256) proj_kernel(
    const float* __restrict__ X, const float* __restrict__ Wt,
    const float* __restrict__ bias, const float* __restrict__ s, int s_idx,
    float* __restrict__ dst)
{
    __shared__ float As[BK][BM + 4];
    __shared__ float Bs[BK][BN];
    const int b  = blockIdx.z;
    const int o0 = blockIdx.y * BM;
    const int n0 = blockIdx.x * BN;
    const int tid = threadIdx.x;
    const int tx = tid & 15, ty = tid >> 4;
    const float* Xb = X + (size_t)b * Cdim * Ndim;

    float acc[8][8];
#pragma unroll
    for (int i = 0; i < 8; i++)
#pragma unroll
        for (int j = 0; j < 8; j++) acc[i][j] = 0.f;

    for (int k0 = 0; k0 < Cdim; k0 += BK) {
        // A tile: W[o0+i][k0+k] -> As[k][i] (transposed store)
#pragma unroll
        for (int r = 0; r < 2; r++) {
            int row = (tid >> 2) + r * 64;
            int kk  = (tid & 3) * 4;
            float4 v = *(const float4*)(Wt + (size_t)(o0 + row) * Cdim + k0 + kk);
            As[kk + 0][row] = v.x; As[kk + 1][row] = v.y;
            As[kk + 2][row] = v.z; As[kk + 3][row] = v.w;
        }
        // B tile: X[b][k0+k][n0+cc] contiguous
#pragma unroll
        for (int r = 0; r < 2; r++) {
            int kk = (tid >> 5) + r * 8;
            int cc = (tid & 31) * 4;
            float4 v = *(const float4*)(Xb + (size_t)(k0 + kk) * Ndim + n0 + cc);
            *(float4*)(&Bs[kk][cc]) = v;
        }
        __syncthreads();
#pragma unroll
        for (int k = 0; k < BK; k++) {
            float a[8], bb[8];
#pragma unroll
            for (int i = 0; i < 8; i++) a[i]  = As[k][ty * 8 + i];
#pragma unroll
            for (int j = 0; j < 8; j++) bb[j] = Bs[k][tx * 8 + j];
#pragma unroll
            for (int i = 0; i < 8; i++)
#pragma unroll
                for (int j = 0; j < 8; j++) acc[i][j] += a[i] * bb[j];
        }
        __syncthreads();
    }

    const float scale = (s_idx >= 0) ? s[s_idx] : 1.f;
#pragma unroll
    for (int i = 0; i < 8; i++) {
        int o = o0 + ty * 8 + i;
        float bi = bias[o];
#pragma unroll
        for (int j = 0; j < 8; j++) {
            int n = n0 + tx * 8 + j;
            dst[((size_t)b * Cdim + o) * Ndim + n] = (acc[i][j] + bi) * scale;
        }
    }
}

// =====================================================================
// scores: S[b][n][m] = (1/16) * sum_c Q[b][c][n] * (Ka[b][c][m] + Kb[b][c][m])
// =====================================================================
__global__ void __launch_bounds__(256) scores_kernel(
    const float* __restrict__ Q, const float* __restrict__ Ka,
    const float* __restrict__ Kb)
{
    __shared__ float As[BK][BM];
    __shared__ float Bs[BK][BN];
    const int b   = blockIdx.z;
    const int nn0 = blockIdx.y * BM;   // query rows
    const int m0  = blockIdx.x * BN;   // key cols
    const int tid = threadIdx.x;
    const int tx = tid & 15, ty = tid >> 4;
    const float* Qb  = Q  + (size_t)b * Cdim * Ndim;
    const float* Kab = Ka + (size_t)b * Cdim * Ndim;
    const float* Kbb = Kb + (size_t)b * Cdim * Ndim;

    float acc[8][8];
#pragma unroll
    for (int i = 0; i < 8; i++)
#pragma unroll
        for (int j = 0; j < 8; j++) acc[i][j] = 0.f;

    for (int k0 = 0; k0 < Cdim; k0 += BK) {
#pragma unroll
        for (int r = 0; r < 2; r++) {
            int kk = (tid >> 5) + r * 8;
            int cc = (tid & 31) * 4;
            float4 qa = *(const float4*)(Qb + (size_t)(k0 + kk) * Ndim + nn0 + cc);
            *(float4*)(&As[kk][cc]) = qa;
            float4 k1 = *(const float4*)(Kab + (size_t)(k0 + kk) * Ndim + m0 + cc);
            float4 k2 = *(const float4*)(Kbb + (size_t)(k0 + kk) * Ndim + m0 + cc);
            k1.x += k2.x; k1.y += k2.y; k1.z += k2.z; k1.w += k2.w;
            *(float4*)(&Bs[kk][cc]) = k1;
        }
        __syncthreads();
#pragma unroll
        for (int k = 0; k < BK; k++) {
            float a[8], bb[8];
#pragma unroll
            for (int i = 0; i < 8; i++) a[i]  = As[k][ty * 8 + i];
#pragma unroll
            for (int j = 0; j < 8; j++) bb[j] = Bs[k][tx * 8 + j];
#pragma unroll
            for (int i = 0; i < 8; i++)
#pragma unroll
                for (int j = 0; j < 8; j++) acc[i][j] += a[i] * bb[j];
        }
        __syncthreads();
    }

    float* Sb = g_S + (size_t)b * Ndim * Ndim;
#pragma unroll
    for (int i = 0; i < 8; i++) {
        int n = nn0 + ty * 8 + i;
#pragma unroll
        for (int j = 0; j < 8; j++) {
            int m = m0 + tx * 8 + j;
            Sb[(size_t)n * Ndim + m] = acc[i][j] * 0.0625f;
        }
    }
}

// =====================================================================
// softmax over last dim (2304 = 9*256), one block per row, in place in g_S
// =====================================================================
__global__ void __launch_bounds__(256) softmax_kernel()
{
    const size_t row = blockIdx.x;
    float* p = g_S + row * Ndim;
    const int tid = threadIdx.x;
    __shared__ float red[256];

    float v[9];
#pragma unroll
    for (int i = 0; i < 9; i++) v[i] = p[tid + i * 256];

    float mx = v[0];
#pragma unroll
    for (int i = 1; i < 9; i++) mx = fmaxf(mx, v[i]);
    red[tid] = mx;
    __syncthreads();
    for (int s = 128; s > 0; s >>= 1) {
        if (tid < s) red[tid] = fmaxf(red[tid], red[tid + s]);
        __syncthreads();
    }
    mx = red[0];
    __syncthreads();

    float sum = 0.f;
#pragma unroll
    for (int i = 0; i < 9; i++) { v[i] = expf(v[i] - mx); sum += v[i]; }
    red[tid] = sum;
    __syncthreads();
    for (int s = 128; s > 0; s >>= 1) {
        if (tid < s) red[tid] += red[tid + s];
        __syncthreads();
    }
    const float inv = 1.f / red[0];
#pragma unroll
    for (int i = 0; i < 9; i++) p[tid + i * 256] = v[i] * inv;
}

// =====================================================================
// AV: dst[b][c][n] = sum_m V[b][c][m] * S[b][n][m]
// =====================================================================
__global__ void __launch_bounds__(256) av_kernel(
    const float* __restrict__ V, float* __restrict__ dst)
{
    __shared__ float As[BK][BM + 4];
    __shared__ float Bs[BK][BN + 4];
    const int b  = blockIdx.z;
    const int c0 = blockIdx.y * BM;
    const int n0 = blockIdx.x * BN;
    const int tid = threadIdx.x;
    const int tx = tid & 15, ty = tid >> 4;
    const float* Vb = V + (size_t)b * Cdim * Ndim;
    const float* Sb = g_S + (size_t)b * Ndim * Ndim;

    float acc[8][8];
#pragma unroll
    for (int i = 0; i < 8; i++)
#pragma unroll
        for (int j = 0; j < 8; j++) acc[i][j] = 0.f;

    for (int k0 = 0; k0 < Ndim; k0 += BK) {
        // A tile: V[c0+i][k0+k] -> As[k][i]
#pragma unroll
        for (int r = 0; r < 2; r++) {
            int row = (tid >> 2) + r * 64;
            int kk  = (tid & 3) * 4;
            float4 v = *(const float4*)(Vb + (size_t)(c0 + row) * Ndim + k0 + kk);
            As[kk + 0][row] = v.x; As[kk + 1][row] = v.y;
            As[kk + 2][row] = v.z; As[kk + 3][row] = v.w;
        }
        // B tile: S[n0+j][k0+k] -> Bs[k][j]
#pragma unroll
        for (int r = 0; r < 2; r++) {
            int row = (tid >> 2) + r * 64;
            int kk  = (tid & 3) * 4;
            float4 v = *(const float4*)(Sb + (size_t)(n0 + row) * Ndim + k0 + kk);
            Bs[kk + 0][row] = v.x; Bs[kk + 1][row] = v.y;
            Bs[kk + 2][row] = v.z; Bs[kk + 3][row] = v.w;
        }
        __syncthreads();
#pragma unroll
        for (int k = 0; k < BK; k++) {
            float a[8], bb[8];
#pragma unroll
            for (int i = 0; i < 8; i++) a[i]  = As[k][ty * 8 + i];
#pragma unroll
            for (int j = 0; j < 8; j++) bb[j] = Bs[k][tx * 8 + j];
#pragma unroll
            for (int i = 0; i < 8; i++)
#pragma unroll
                for (int j = 0; j < 8; j++) acc[i][j] += a[i] * bb[j];
        }
        __syncthreads();
    }

#pragma unroll
    for (int i = 0; i < 8; i++) {
        int c = c0 + ty * 8 + i;
#pragma unroll
        for (int j = 0; j < 8; j++) {
            int n = n0 + tx * 8 + j;
            dst[((size_t)b * Cdim + c) * Ndim + n] = acc[i][j];
        }
    }
}

// =====================================================================
// gate: F[b][o][n] (+)= sigmoid( sum_c Wg[o][c]*X[b][c][n] + bg[o] ) * X[b][o][n]
// =====================================================================
__global__ void __launch_bounds__(256) gate_kernel(
    const float* __restrict__ X, const float* __restrict__ Wg,
    const float* __restrict__ bg, float* __restrict__ F, int accumulate)
{
    __shared__ float As[BK][BM + 4];
    __shared__ float Bs[BK][BN];
    const int b  = blockIdx.z;
    const int o0 = blockIdx.y * BM;
    const int n0 = blockIdx.x * BN;
    const int tid = threadIdx.x;
    const int tx = tid & 15, ty = tid >> 4;
    const float* Xb = X + (size_t)b * Cdim * Ndim;

    float acc[8][8];
#pragma unroll
    for (int i = 0; i < 8; i++)
#pragma unroll
        for (int j = 0; j < 8; j++) acc[i][j] = 0.f;

    for (int k0 = 0; k0 < Cdim; k0 += BK) {
#pragma unroll
        for (int r = 0; r < 2; r++) {
            int row = (tid >> 2) + r * 64;
            int kk  = (tid & 3) * 4;
            float4 v = *(const float4*)(Wg + (size_t)(o0 + row) * Cdim + k0 + kk);
            As[kk + 0][row] = v.x; As[kk + 1][row] = v.y;
            As[kk + 2][row] = v.z; As[kk + 3][row] = v.w;
        }
#pragma unroll
        for (int r = 0; r < 2; r++) {
            int kk = (tid >> 5) + r * 8;
            int cc = (tid & 31) * 4;
            float4 v = *(const float4*)(Xb + (size_t)(k0 + kk) * Ndim + n0 + cc);
            *(float4*)(&Bs[kk][cc]) = v;
        }
        __syncthreads();
#pragma unroll
        for (int k = 0; k < BK; k++) {
            float a[8], bb[8];
#pragma unroll
            for (int i = 0; i < 8; i++) a[i]  = As[k][ty * 8 + i];
#pragma unroll
            for (int j = 0; j < 8; j++) bb[j] = Bs[k][tx * 8 + j];
#pragma unroll
            for (int i = 0; i < 8; i++)
#pragma unroll
                for (int j = 0; j < 8; j++) acc[i][j] += a[i] * bb[j];
        }
        __syncthreads();
    }

#pragma unroll
    for (int i = 0; i < 8; i++) {
        int o = o0 + ty * 8 + i;
        float bi = bg[o];
#pragma unroll
        for (int j = 0; j < 8; j++) {
            int n = n0 + tx * 8 + j;
            size_t idx = ((size_t)b * Cdim + o) * Ndim + n;
            float g   = acc[i][j] + bi;
            float sig = 1.f / (1.f + expf(-g));
            float val = sig * X[idx];
            if (accumulate) F[idx] += val;
            else            F[idx]  = val;
        }
    }
}

// =====================================================================
// launch
// =====================================================================
extern "C" void kernel_launch(void* const* d_in, const int* in_sizes, int n_in,
                              void* d_out, int out_size)
{
    const float* x[3] = { (const float*)d_in[0], (const float*)d_in[1], (const float*)d_in[2] };
    const float* s = (const float*)d_in[3];
    const float *wq[3], *bq[3], *wk[3], *bk[3], *wv[3], *bv[3];
    for (int m = 0; m < 3; m++) {
        wq[m] = (const float*)d_in[4 + 6 * m];
        bq[m] = (const float*)d_in[5 + 6 * m];
        wk[m] = (const float*)d_in[6 + 6 * m];
        bk[m] = (const float*)d_in[7 + 6 * m];
        wv[m] = (const float*)d_in[8 + 6 * m];
        bv[m] = (const float*)d_in[9 + 6 * m];
    }
    const float* wg = (const float*)d_in[22];
    const float* bg = (const float*)d_in[23];
    const float* wo = (const float*)d_in[24];
    const float* bo = (const float*)d_in[25];
    float* out = (float*)d_out;

    float *gP, *gW, *gF;
    cudaGetSymbolAddress((void**)&gP, g_P);
    cudaGetSymbolAddress((void**)&gW, g_W);
    cudaGetSymbolAddress((void**)&gF, g_F);

    float* Q[3]; float* K[3]; float* V[3]; float* Wout[3];
    for (int m = 0; m < 3; m++) {
        Q[m]    = gP + (size_t)(0 + m) * PLANE;
        K[m]    = gP + (size_t)(3 + m) * PLANE;
        V[m]    = gP + (size_t)(6 + m) * PLANE;
        Wout[m] = gW + (size_t)m * PLANE;
    }

    dim3 blk(256);
    dim3 gProj(Ndim / BN, Cdim / BM, Bdim);    // 18 x 2 x 4
    dim3 gScore(Ndim / BN, Ndim / BM, Bdim);   // 18 x 18 x 4
    dim3 gSoft(Bdim * Ndim);                   // 9216

    // projections (Q,K scaled by s[m]; V unscaled)
    for (int m = 0; m < 3; m++) {
        proj_kernel<<<gProj, blk>>>(x[m], wq[m], bq[m], s, m, Q[m]);
        proj_kernel<<<gProj, blk>>>(x[m], wk[m], bk[m], s, m, K[m]);
        proj_kernel<<<gProj, blk>>>(x[m], wv[m], bv[m], s, -1, V[m]);
    }

    // attends: w_rgb(Q0; K2+K1; V0), w_depth(Q2; K0+K1; V2), w_thermal(Q1; K0+K2; V1)
    const int qi[3]  = { 0, 2, 1 };
    const int kai[3] = { 2, 0, 0 };
    const int kbi[3] = { 1, 1, 2 };
    const int vi[3]  = { 0, 2, 1 };
    for (int a = 0; a < 3; a++) {
        scores_kernel<<<gScore, blk>>>(Q[qi[a]], K[kai[a]], K[kbi[a]]);
        softmax_kernel<<<gSoft, blk>>>();
        av_kernel<<<gProj, blk>>>(V[vi[a]], Wout[a]);
    }

    // gated fusion
    for (int m = 0; m < 3; m++)
        gate_kernel<<<gProj, blk>>>(Wout[m], wg, bg, gF, m > 0 ? 1 : 0);

    // final 1x1 conv -> d_out
    proj_kernel<<<gProj, blk>>>(gF, wo, bo, s, -1, out);
}

// round 3
// speedup vs baseline: 2.1980x; 2.1980x over previous
#include <cuda_runtime.h>
#include <cstdint>
#include <math.h>

#define Bdim 4
#define Cdim 256
#define Ndim 2304      // 48*48
#define PLANE (Bdim*Cdim*Ndim)

#define BM 128
#define BN 128
#define BK 16
#define BMP 136        // padded smem stride (conflict-free frag loads)

// ---- scratch (device globals; allocation-free) ----
__device__ float g_P[9][PLANE];                    // Q0..2, K0..2, V0..2
__device__ float g_S[(size_t)Bdim * Ndim * Ndim];  // scores (reused)
__device__ float g_W[3][PLANE];                    // attention outputs
__device__ float g_F[PLANE];                       // gated fused sum

// ---- tf32 helpers ----
__device__ __forceinline__ float f2tf32f(float x) {
    uint32_t u;
    asm("cvt.rna.tf32.f32 %0, %1;" : "=r"(u) : "f"(x));
    return __uint_as_float(u);
}

__device__ __forceinline__ void mma_tf32(float c[4], const uint32_t a[4], const uint32_t b[2]) {
    asm volatile(
        "mma.sync.aligned.m16n8k8.row.col.f32.tf32.tf32.f32 "
        "{%0,%1,%2,%3}, {%4,%5,%6,%7}, {%8,%9}, {%0,%1,%2,%3};"
        : "+f"(c[0]), "+f"(c[1]), "+f"(c[2]), "+f"(c[3])
        : "r"(a[0]), "r"(a[1]), "r"(a[2]), "r"(a[3]), "r"(b[0]), "r"(b[1]));
}

// Compute one 128x128 tile's worth of MMAs for the two k8 sub-steps in smem.
// Layouts: As[k][m] stride BMP, Bs[k][n] stride BMP. Warp tile 64x32.
__device__ __forceinline__ void tile_mma(
    const float (*As)[BMP], const float (*Bs)[BMP],
    int wm, int wn, int g, int t, float acc[4][4][4])
{
#pragma unroll
    for (int ks = 0; ks < BK; ks += 8) {
        uint32_t af[4][4], bf[4][2];
#pragma unroll
        for (int mi = 0; mi < 4; mi++) {
            int m = wm + mi * 16 + g;
            af[mi][0] = __float_as_uint(As[ks + t][m]);
            af[mi][1] = __float_as_uint(As[ks + t][m + 8]);
            af[mi][2] = __float_as_uint(As[ks + t + 4][m]);
            af[mi][3] = __float_as_uint(As[ks + t + 4][m + 8]);
        }
#pragma unroll
        for (int ni = 0; ni < 4; ni++) {
            int n = wn + ni * 8 + g;
            bf[ni][0] = __float_as_uint(Bs[ks + t][n]);
            bf[ni][1] = __float_as_uint(Bs[ks + t + 4][n]);
        }
#pragma unroll
        for (int mi = 0; mi < 4; mi++)
#pragma unroll
            for (int ni = 0; ni < 4; ni++)
                mma_tf32(acc[mi][ni], af[mi], bf[ni]);
    }
}

// =====================================================================
// proj: dst[b][o][n] = scale * ( sum_c W[o][c] * X[b][c][n] + bias[o] )
// A = W (transpose into [k][m]), B = X (natural [k][n])
// =====================================================================
__global__ void __launch_bounds__(256, 2) proj_mma(
    const float* __restrict__ X, const float* __restrict__ Wt,
    const float* __restrict__ bias, const float* __restrict__ s, int s_idx,
    float* __restrict__ dst)
{
    __shared__ float As[BK][BMP];
    __shared__ float Bs[BK][BMP];
    const int b  = blockIdx.z;
    const int o0 = blockIdx.y * BM;
    const int n0 = blockIdx.x * BN;
    const int tid = threadIdx.x;
    const int warp = tid >> 5, lane = tid & 31;
    const int g = lane >> 2, t = lane & 3;
    const int wm = (warp & 1) * 64, wn = (warp >> 1) * 32;
    const float* Xb = X + (size_t)b * Cdim * Ndim;

    // A loader indices (transpose): row=o, kk chunk
    const int arow = tid >> 1;
    const int akk0 = (tid & 1) * 8;
    // B loader indices: k row, n chunk
    const int bn4 = (tid & 31) * 4;
    const int bk0 = tid >> 5;

    float acc[4][4][4];
#pragma unroll
    for (int mi = 0; mi < 4; mi++)
#pragma unroll
        for (int ni = 0; ni < 4; ni++)
#pragma unroll
            for (int r = 0; r < 4; r++) acc[mi][ni][r] = 0.f;

    float4 a_st[2], b_st[2];
    auto loadg = [&](int k0) {
#pragma unroll
        for (int r = 0; r < 2; r++)
            a_st[r] = *(const float4*)(Wt + (size_t)(o0 + arow) * Cdim + k0 + akk0 + r * 4);
#pragma unroll
        for (int r = 0; r < 2; r++)
            b_st[r] = *(const float4*)(Xb + (size_t)(k0 + bk0 + r * 8) * Ndim + n0 + bn4);
    };
    auto storeg = [&]() {
#pragma unroll
        for (int r = 0; r < 2; r++) {
            int kk = akk0 + r * 4;
            As[kk + 0][arow] = f2tf32f(a_st[r].x);
            As[kk + 1][arow] = f2tf32f(a_st[r].y);
            As[kk + 2][arow] = f2tf32f(a_st[r].z);
            As[kk + 3][arow] = f2tf32f(a_st[r].w);
        }
#pragma unroll
        for (int r = 0; r < 2; r++) {
            float4 v = b_st[r];
            v.x = f2tf32f(v.x); v.y = f2tf32f(v.y);
            v.z = f2tf32f(v.z); v.w = f2tf32f(v.w);
            *(float4*)(&Bs[bk0 + r * 8][bn4]) = v;
        }
    };

    loadg(0); storeg(); __syncthreads();
    for (int k0 = 0; k0 < Cdim; k0 += BK) {
        bool more = (k0 + BK) < Cdim;
        if (more) loadg(k0 + BK);
        tile_mma(As, Bs, wm, wn, g, t, acc);
        __syncthreads();
        if (more) { storeg(); __syncthreads(); }
    }

    const float scale = (s_idx >= 0) ? s[s_idx] : 1.f;
#pragma unroll
    for (int mi = 0; mi < 4; mi++)
#pragma unroll
        for (int r2 = 0; r2 < 2; r2++) {
            int m = o0 + wm + mi * 16 + g + r2 * 8;
            float bi = bias[m];
#pragma unroll
            for (int ni = 0; ni < 4; ni++) {
                int n = n0 + wn + ni * 8 + t * 2;
                size_t idx = ((size_t)b * Cdim + m) * Ndim + n;
                dst[idx]     = (acc[mi][ni][r2 * 2 + 0] + bi) * scale;
                dst[idx + 1] = (acc[mi][ni][r2 * 2 + 1] + bi) * scale;
            }
        }
}

// =====================================================================
// scores: S[b][y][z] = (1/16) * sum_c Q[b][c][y] * (Ka[b][c][z]+Kb[b][c][z])
// A = Q (natural [k][m]), B = Ka+Kb (natural [k][n])
// =====================================================================
__global__ void __launch_bounds__(256, 2) scores_mma(
    const float* __restrict__ Q, const float* __restrict__ Ka,
    const float* __restrict__ Kb)
{
    __shared__ float As[BK][BMP];
    __shared__ float Bs[BK][BMP];
    const int b  = blockIdx.z;
    const int y0 = blockIdx.y * BM;
    const int z0 = blockIdx.x * BN;
    const int tid = threadIdx.x;
    const int warp = tid >> 5, lane = tid & 31;
    const int g = lane >> 2, t = lane & 3;
    const int wm = (warp & 1) * 64, wn = (warp >> 1) * 32;
    const float* Qb  = Q  + (size_t)b * Cdim * Ndim;
    const float* Kab = Ka + (size_t)b * Cdim * Ndim;
    const float* Kbb = Kb + (size_t)b * Cdim * Ndim;

    const int n4 = (tid & 31) * 4;
    const int k0r = tid >> 5;

    float acc[4][4][4];
#pragma unroll
    for (int mi = 0; mi < 4; mi++)
#pragma unroll
        for (int ni = 0; ni < 4; ni++)
#pragma unroll
            for (int r = 0; r < 4; r++) acc[mi][ni][r] = 0.f;

    float4 a_st[2], b_st[2];
    auto loadg = [&](int k0) {
#pragma unroll
        for (int r = 0; r < 2; r++) {
            size_t koff = (size_t)(k0 + k0r + r * 8) * Ndim;
            a_st[r] = *(const float4*)(Qb + koff + y0 + n4);
            float4 v1 = *(const float4*)(Kab + koff + z0 + n4);
            float4 v2 = *(const float4*)(Kbb + koff + z0 + n4);
            v1.x += v2.x; v1.y += v2.y; v1.z += v2.z; v1.w += v2.w;
            b_st[r] = v1;
        }
    };
    auto storeg = [&]() {
#pragma unroll
        for (int r = 0; r < 2; r++) {
            float4 va = a_st[r];
            va.x = f2tf32f(va.x); va.y = f2tf32f(va.y);
            va.z = f2tf32f(va.z); va.w = f2tf32f(va.w);
            *(float4*)(&As[k0r + r * 8][n4]) = va;
            float4 vb = b_st[r];
            vb.x = f2tf32f(vb.x); vb.y = f2tf32f(vb.y);
            vb.z = f2tf32f(vb.z); vb.w = f2tf32f(vb.w);
            *(float4*)(&Bs[k0r + r * 8][n4]) = vb;
        }
    };

    loadg(0); storeg(); __syncthreads();
    for (int k0 = 0; k0 < Cdim; k0 += BK) {
        bool more = (k0 + BK) < Cdim;
        if (more) loadg(k0 + BK);
        tile_mma(As, Bs, wm, wn, g, t, acc);
        __syncthreads();
        if (more) { storeg(); __syncthreads(); }
    }

    float* Sb = g_S + (size_t)b * Ndim * Ndim;
#pragma unroll
    for (int mi = 0; mi < 4; mi++)
#pragma unroll
        for (int r2 = 0; r2 < 2; r2++) {
            int y = y0 + wm + mi * 16 + g + r2 * 8;
#pragma unroll
            for (int ni = 0; ni < 4; ni++) {
                int z = z0 + wn + ni * 8 + t * 2;
                size_t idx = (size_t)y * Ndim + z;
                Sb[idx]     = acc[mi][ni][r2 * 2 + 0] * 0.0625f;
                Sb[idx + 1] = acc[mi][ni][r2 * 2 + 1] * 0.0625f;
            }
        }
}

// =====================================================================
// softmax over last dim (2304 = 9*256), one block per row, in place
// =====================================================================
__global__ void __launch_bounds__(256) softmax_kernel()
{
    const size_t row = blockIdx.x;
    float* p = g_S + row * Ndim;
    const int tid = threadIdx.x;
    __shared__ float red[256];

    float v[9];
#pragma unroll
    for (int i = 0; i < 9; i++) v[i] = p[tid + i * 256];

    float mx = v[0];
#pragma unroll
    for (int i = 1; i < 9; i++) mx = fmaxf(mx, v[i]);
    red[tid] = mx;
    __syncthreads();
    for (int s = 128; s > 0; s >>= 1) {
        if (tid < s) red[tid] = fmaxf(red[tid], red[tid + s]);
        __syncthreads();
    }
    mx = red[0];
    __syncthreads();

    float sum = 0.f;
#pragma unroll
    for (int i = 0; i < 9; i++) { v[i] = expf(v[i] - mx); sum += v[i]; }
    red[tid] = sum;
    __syncthreads();
    for (int s = 128; s > 0; s >>= 1) {
        if (tid < s) red[tid] += red[tid + s];
        __syncthreads();
    }
    const float inv = 1.f / red[0];
#pragma unroll
    for (int i = 0; i < 9; i++) p[tid + i * 256] = v[i] * inv;
}

// =====================================================================
// AV: dst[b][c][n] = sum_m V[b][c][m] * S[b][n][m]
// A = V (transpose [k][m]), B = S (transpose [k][n]); K = Ndim
// =====================================================================
__global__ void __launch_bounds__(256, 2) av_mma(
    const float* __restrict__ V, float* __restrict__ dst)
{
    __shared__ float As[BK][BMP];
    __shared__ float Bs[BK][BMP];
    const int b  = blockIdx.z;
    const int c0 = blockIdx.y * BM;
    const int n0 = blockIdx.x * BN;
    const int tid = threadIdx.x;
    const int warp = tid >> 5, lane = tid & 31;
    const int g = lane >> 2, t = lane & 3;
    const int wm = (warp & 1) * 64, wn = (warp >> 1) * 32;
    const float* Vb = V + (size_t)b * Cdim * Ndim;
    const float* Sb = g_S + (size_t)b * Ndim * Ndim;

    const int row = tid >> 1;
    const int kk0 = (tid & 1) * 8;

    float acc[4][4][4];
#pragma unroll
    for (int mi = 0; mi < 4; mi++)
#pragma unroll
        for (int ni = 0; ni < 4; ni++)
#pragma unroll
            for (int r = 0; r < 4; r++) acc[mi][ni][r] = 0.f;

    float4 a_st[2], b_st[2];
    auto loadg = [&](int k0) {
#pragma unroll
        for (int r = 0; r < 2; r++) {
            a_st[r] = *(const float4*)(Vb + (size_t)(c0 + row) * Ndim + k0 + kk0 + r * 4);
            b_st[r] = *(const float4*)(Sb + (size_t)(n0 + row) * Ndim + k0 + kk0 + r * 4);
        }
    };
    auto storeg = [&]() {
#pragma unroll
        for (int r = 0; r < 2; r++) {
            int kk = kk0 + r * 4;
            As[kk + 0][row] = f2tf32f(a_st[r].x);
            As[kk + 1][row] = f2tf32f(a_st[r].y);
            As[kk + 2][row] = f2tf32f(a_st[r].z);
            As[kk + 3][row] = f2tf32f(a_st[r].w);
            Bs[kk + 0][row] = f2tf32f(b_st[r].x);
            Bs[kk + 1][row] = f2tf32f(b_st[r].y);
            Bs[kk + 2][row] = f2tf32f(b_st[r].z);
            Bs[kk + 3][row] = f2tf32f(b_st[r].w);
        }
    };

    loadg(0); storeg(); __syncthreads();
    for (int k0 = 0; k0 < Ndim; k0 += BK) {
        bool more = (k0 + BK) < Ndim;
        if (more) loadg(k0 + BK);
        tile_mma(As, Bs, wm, wn, g, t, acc);
        __syncthreads();
        if (more) { storeg(); __syncthreads(); }
    }

#pragma unroll
    for (int mi = 0; mi < 4; mi++)
#pragma unroll
        for (int r2 = 0; r2 < 2; r2++) {
            int c = c0 + wm + mi * 16 + g + r2 * 8;
#pragma unroll
            for (int ni = 0; ni < 4; ni++) {
                int n = n0 + wn + ni * 8 + t * 2;
                size_t idx = ((size_t)b * Cdim + c) * Ndim + n;
                dst[idx]     = acc[mi][ni][r2 * 2 + 0];
                dst[idx + 1] = acc[mi][ni][r2 * 2 + 1];
            }
        }
}

// =====================================================================
// gate: F[b][o][n] (+)= sigmoid( sum_c Wg[o][c]*X[b][c][n] + bg[o] ) * X[b][o][n]
// =====================================================================
__global__ void __launch_bounds__(256, 2) gate_mma(
    const float* __restrict__ X, const float* __restrict__ Wg,
    const float* __restrict__ bg, float* __restrict__ F, int accumulate)
{
    __shared__ float As[BK][BMP];
    __shared__ float Bs[BK][BMP];
    const int b  = blockIdx.z;
    const int o0 = blockIdx.y * BM;
    const int n0 = blockIdx.x * BN;
    const int tid = threadIdx.x;
    const int warp = tid >> 5, lane = tid & 31;
    const int g = lane >> 2, t = lane & 3;
    const int wm = (warp & 1) * 64, wn = (warp >> 1) * 32;
    const float* Xb = X + (size_t)b * Cdim * Ndim;

    const int arow = tid >> 1;
    const int akk0 = (tid & 1) * 8;
    const int bn4 = (tid & 31) * 4;
    const int bk0 = tid >> 5;

    float acc[4][4][4];
#pragma unroll
    for (int mi = 0; mi < 4; mi++)
#pragma unroll
        for (int ni = 0; ni < 4; ni++)
#pragma unroll
            for (int r = 0; r < 4; r++) acc[mi][ni][r] = 0.f;

    float4 a_st[2], b_st[2];
    auto loadg = [&](int k0) {
#pragma unroll
        for (int r = 0; r < 2; r++)
            a_st[r] = *(const float4*)(Wg + (size_t)(o0 + arow) * Cdim + k0 + akk0 + r * 4);
#pragma unroll
        for (int r = 0; r < 2; r++)
            b_st[r] = *(const float4*)(Xb + (size_t)(k0 + bk0 + r * 8) * Ndim + n0 + bn4);
    };
    auto storeg = [&]() {
#pragma unroll
        for (int r = 0; r < 2; r++) {
            int kk = akk0 + r * 4;
            As[kk + 0][arow] = f2tf32f(a_st[r].x);
            As[kk + 1][arow] = f2tf32f(a_st[r].y);
            As[kk + 2][arow] = f2tf32f(a_st[r].z);
            As[kk + 3][arow] = f2tf32f(a_st[r].w);
        }
#pragma unroll
        for (int r = 0; r < 2; r++) {
            float4 v = b_st[r];
            v.x = f2tf32f(v.x); v.y = f2tf32f(v.y);
            v.z = f2tf32f(v.z); v.w = f2tf32f(v.w);
            *(float4*)(&Bs[bk0 + r * 8][bn4]) = v;
        }
    };

    loadg(0); storeg(); __syncthreads();
    for (int k0 = 0; k0 < Cdim; k0 += BK) {
        bool more = (k0 + BK) < Cdim;
        if (more) loadg(k0 + BK);
        tile_mma(As, Bs, wm, wn, g, t, acc);
        __syncthreads();
        if (more) { storeg(); __syncthreads(); }
    }

#pragma unroll
    for (int mi = 0; mi < 4; mi++)
#pragma unroll
        for (int r2 = 0; r2 < 2; r2++) {
            int o = o0 + wm + mi * 16 + g + r2 * 8;
            float bi = bg[o];
#pragma unroll
            for (int ni = 0; ni < 4; ni++) {
                int n = n0 + wn + ni * 8 + t * 2;
                size_t idx = ((size_t)b * Cdim + o) * Ndim + n;
#pragma unroll
                for (int e = 0; e < 2; e++) {
                    float gv  = acc[mi][ni][r2 * 2 + e] + bi;
                    float sig = 1.f / (1.f + expf(-gv));
                    float val = sig * X[idx + e];
                    if (accumulate) F[idx + e] += val;
                    else            F[idx + e]  = val;
                }
            }
        }
}

// =====================================================================
// launch
// =====================================================================
extern "C" void kernel_launch(void* const* d_in, const int* in_sizes, int n_in,
                              void* d_out, int out_size)
{
    const float* x[3] = { (const float*)d_in[0], (const float*)d_in[1], (const float*)d_in[2] };
    const float* s = (const float*)d_in[3];
    const float *wq[3], *bq[3], *wk[3], *bk[3], *wv[3], *bv[3];
    for (int m = 0; m < 3; m++) {
        wq[m] = (const float*)d_in[4 + 6 * m];
        bq[m] = (const float*)d_in[5 + 6 * m];
        wk[m] = (const float*)d_in[6 + 6 * m];
        bk[m] = (const float*)d_in[7 + 6 * m];
        wv[m] = (const float*)d_in[8 + 6 * m];
        bv[m] = (const float*)d_in[9 + 6 * m];
    }
    const float* wg = (const float*)d_in[22];
    const float* bg = (const float*)d_in[23];
    const float* wo = (const float*)d_in[24];
    const float* bo = (const float*)d_in[25];
    float* out = (float*)d_out;

    float *gP, *gW, *gF;
    cudaGetSymbolAddress((void**)&gP, g_P);
    cudaGetSymbolAddress((void**)&gW, g_W);
    cudaGetSymbolAddress((void**)&gF, g_F);

    float* Q[3]; float* K[3]; float* V[3]; float* Wout[3];
    for (int m = 0; m < 3; m++) {
        Q[m]    = gP + (size_t)(0 + m) * PLANE;
        K[m]    = gP + (size_t)(3 + m) * PLANE;
        V[m]    = gP + (size_t)(6 + m) * PLANE;
        Wout[m] = gW + (size_t)m * PLANE;
    }

    dim3 blk(256);
    dim3 gProj(Ndim / BN, Cdim / BM, Bdim);    // 18 x 2 x 4
    dim3 gScore(Ndim / BN, Ndim / BM, Bdim);   // 18 x 18 x 4
    dim3 gSoft(Bdim * Ndim);

    for (int m = 0; m < 3; m++) {
        proj_mma<<<gProj, blk>>>(x[m], wq[m], bq[m], s, m, Q[m]);
        proj_mma<<<gProj, blk>>>(x[m], wk[m], bk[m], s, m, K[m]);
        proj_mma<<<gProj, blk>>>(x[m], wv[m], bv[m], s, -1, V[m]);
    }

    // attends: w_rgb(Q0; K2+K1; V0), w_depth(Q2; K0+K1; V2), w_thermal(Q1; K0+K2; V1)
    const int qi[3]  = { 0, 2, 1 };
    const int kai[3] = { 2, 0, 0 };
    const int kbi[3] = { 1, 1, 2 };
    const int vi[3]  = { 0, 2, 1 };
    for (int a = 0; a < 3; a++) {
        scores_mma<<<gScore, blk>>>(Q[qi[a]], K[kai[a]], K[kbi[a]]);
        softmax_kernel<<<gSoft, blk>>>();
        av_mma<<<gProj, blk>>>(V[vi[a]], Wout[a]);
    }

    for (int m = 0; m < 3; m++)
        gate_mma<<<gProj, blk>>>(Wout[m], wg, bg, gF, m > 0 ? 1 : 0);

    proj_mma<<<gProj, blk>>>(gF, wo, bo, s, -1, out);
}

// round 4
// speedup vs baseline: 2.6338x; 1.1982x over previous
#include <cuda_runtime.h>
#include <cstdint>
#include <math.h>

#define Bdim 4
#define Cdim 256
#define Ndim 2304      // 48*48
#define PLANE (Bdim*Cdim*Ndim)
#define CN   (Cdim*Ndim)
#define NN   ((size_t)Ndim*Ndim)

#define BM 128
#define BN 128
#define BK 16
#define BMP 136        // padded smem stride

// ---- scratch ----
__device__ float g_P[9][PLANE];                      // Q0..2, K0..2, V0..2
__device__ float g_S3[(size_t)3 * Bdim * NN];        // scores for all 3 attends
__device__ float g_W[3][PLANE];                      // attention outputs
__device__ float g_F3[3][PLANE];                     // gated outputs (summed by final conv)

// ---- tf32 helpers ----
__device__ __forceinline__ float f2tf32f(float x) {
    uint32_t u;
    asm("cvt.rna.tf32.f32 %0, %1;" : "=r"(u) : "f"(x));
    return __uint_as_float(u);
}

__device__ __forceinline__ void mma_tf32(float c[4], const uint32_t a[4], const uint32_t b[2]) {
    asm volatile(
        "mma.sync.aligned.m16n8k8.row.col.f32.tf32.tf32.f32 "
        "{%0,%1,%2,%3}, {%4,%5,%6,%7}, {%8,%9}, {%0,%1,%2,%3};"
        : "+f"(c[0]), "+f"(c[1]), "+f"(c[2]), "+f"(c[3])
        : "r"(a[0]), "r"(a[1]), "r"(a[2]), "r"(a[3]), "r"(b[0]), "r"(b[1]));
}

__device__ __forceinline__ void tile_mma(
    const float (*As)[BMP], const float (*Bs)[BMP],
    int wm, int wn, int g, int t, float acc[4][4][4])
{
#pragma unroll
    for (int ks = 0; ks < BK; ks += 8) {
        uint32_t af[4][4], bf[4][2];
#pragma unroll
        for (int mi = 0; mi < 4; mi++) {
            int m = wm + mi * 16 + g;
            af[mi][0] = __float_as_uint(As[ks + t][m]);
            af[mi][1] = __float_as_uint(As[ks + t][m + 8]);
            af[mi][2] = __float_as_uint(As[ks + t + 4][m]);
            af[mi][3] = __float_as_uint(As[ks + t + 4][m + 8]);
        }
#pragma unroll
        for (int ni = 0; ni < 4; ni++) {
            int n = wn + ni * 8 + g;
            bf[ni][0] = __float_as_uint(Bs[ks + t][n]);
            bf[ni][1] = __float_as_uint(Bs[ks + t + 4][n]);
        }
#pragma unroll
        for (int mi = 0; mi < 4; mi++)
#pragma unroll
            for (int ni = 0; ni < 4; ni++)
                mma_tf32(acc[mi][ni], af[mi], bf[ni]);
    }
}

#define DECL_ACC float acc[4][4][4]; \
    _Pragma("unroll") for (int mi = 0; mi < 4; mi++) \
    _Pragma("unroll") for (int ni = 0; ni < 4; ni++) \
    _Pragma("unroll") for (int r = 0; r < 4; r++) acc[mi][ni][r] = 0.f;

// ---- batched arg structs ----
struct Proj9 {
    const float* X[9]; const float* W[9]; const float* B[9];
    float* D[9]; int sidx[9];
};
struct Att3 {
    const float* Q[3]; const float* Ka[3]; const float* Kb[3];
    const float* V[3]; float* O[3];
};

// =====================================================================
// batched proj: z = job*4 + b   (grid z = 36)
// =====================================================================
__global__ void __launch_bounds__(256, 2) proj_mma9(Proj9 P, const float* __restrict__ s)
{
    __shared__ float As[2][BK][BMP];
    __shared__ float Bs[2][BK][BMP];
    const int z = blockIdx.z, job = z >> 2, b = z & 3;
    const int o0 = blockIdx.y * BM;
    const int n0 = blockIdx.x * BN;
    const int tid = threadIdx.x;
    const int warp = tid >> 5, lane = tid & 31;
    const int g = lane >> 2, t = lane & 3;
    const int wm = (warp & 1) * 64, wn = (warp >> 1) * 32;

    const float* Xb   = P.X[job] + (size_t)b * CN;
    const float* Wt   = P.W[job];
    const float* bias = P.B[job];
    float*       dst  = P.D[job] + (size_t)b * CN;
    const int   sidx  = P.sidx[job];

    const int arow = tid >> 1;
    const int akk0 = (tid & 1) * 8;
    const int bn4 = (tid & 31) * 4;
    const int bk0 = tid >> 5;

    DECL_ACC;

    float4 a_st[2], b_st[2];
    auto loadg = [&](int k0) {
#pragma unroll
        for (int r = 0; r < 2; r++)
            a_st[r] = *(const float4*)(Wt + (size_t)(o0 + arow) * Cdim + k0 + akk0 + r * 4);
#pragma unroll
        for (int r = 0; r < 2; r++)
            b_st[r] = *(const float4*)(Xb + (size_t)(k0 + bk0 + r * 8) * Ndim + n0 + bn4);
    };
    auto storeg = [&](int buf) {
#pragma unroll
        for (int r = 0; r < 2; r++) {
            int kk = akk0 + r * 4;
            As[buf][kk + 0][arow] = f2tf32f(a_st[r].x);
            As[buf][kk + 1][arow] = f2tf32f(a_st[r].y);
            As[buf][kk + 2][arow] = f2tf32f(a_st[r].z);
            As[buf][kk + 3][arow] = f2tf32f(a_st[r].w);
        }
#pragma unroll
        for (int r = 0; r < 2; r++) {
            float4 v = b_st[r];
            v.x = f2tf32f(v.x); v.y = f2tf32f(v.y);
            v.z = f2tf32f(v.z); v.w = f2tf32f(v.w);
            *(float4*)(&Bs[buf][bk0 + r * 8][bn4]) = v;
        }
    };

    loadg(0); storeg(0); __syncthreads();
    int buf = 0;
    for (int k0 = 0; k0 < Cdim; k0 += BK) {
        bool more = (k0 + BK) < Cdim;
        if (more) loadg(k0 + BK);
        tile_mma(As[buf], Bs[buf], wm, wn, g, t, acc);
        if (more) storeg(buf ^ 1);
        __syncthreads();
        buf ^= 1;
    }

    const float scale = (sidx >= 0) ? s[sidx] : 1.f;
#pragma unroll
    for (int mi = 0; mi < 4; mi++)
#pragma unroll
        for (int r2 = 0; r2 < 2; r2++) {
            int m = o0 + wm + mi * 16 + g + r2 * 8;
            float bi = bias[m];
#pragma unroll
            for (int ni = 0; ni < 4; ni++) {
                int n = n0 + wn + ni * 8 + t * 2;
                size_t idx = (size_t)m * Ndim + n;
                dst[idx]     = (acc[mi][ni][r2 * 2 + 0] + bi) * scale;
                dst[idx + 1] = (acc[mi][ni][r2 * 2 + 1] + bi) * scale;
            }
        }
}

// =====================================================================
// batched scores: z = attend*4 + b (grid z = 12)
// S3[z][y][m] = (1/16) sum_c Q[c][y]*(Ka[c][m]+Kb[c][m])
// =====================================================================
__global__ void __launch_bounds__(256, 2) scores_mma3(Att3 A)
{
    __shared__ float As[2][BK][BMP];
    __shared__ float Bs[2][BK][BMP];
    const int z = blockIdx.z, a = z >> 2, b = z & 3;
    const int y0 = blockIdx.y * BM;
    const int z0 = blockIdx.x * BN;
    const int tid = threadIdx.x;
    const int warp = tid >> 5, lane = tid & 31;
    const int g = lane >> 2, t = lane & 3;
    const int wm = (warp & 1) * 64, wn = (warp >> 1) * 32;
    const float* Qb  = A.Q[a]  + (size_t)b * CN;
    const float* Kab = A.Ka[a] + (size_t)b * CN;
    const float* Kbb = A.Kb[a] + (size_t)b * CN;

    const int n4 = (tid & 31) * 4;
    const int k0r = tid >> 5;

    DECL_ACC;

    float4 a_st[2], b_st[2];
    auto loadg = [&](int k0) {
#pragma unroll
        for (int r = 0; r < 2; r++) {
            size_t koff = (size_t)(k0 + k0r + r * 8) * Ndim;
            a_st[r] = *(const float4*)(Qb + koff + y0 + n4);
            float4 v1 = *(const float4*)(Kab + koff + z0 + n4);
            float4 v2 = *(const float4*)(Kbb + koff + z0 + n4);
            v1.x += v2.x; v1.y += v2.y; v1.z += v2.z; v1.w += v2.w;
            b_st[r] = v1;
        }
    };
    auto storeg = [&](int buf) {
#pragma unroll
        for (int r = 0; r < 2; r++) {
            float4 va = a_st[r];
            va.x = f2tf32f(va.x); va.y = f2tf32f(va.y);
            va.z = f2tf32f(va.z); va.w = f2tf32f(va.w);
            *(float4*)(&As[buf][k0r + r * 8][n4]) = va;
            float4 vb = b_st[r];
            vb.x = f2tf32f(vb.x); vb.y = f2tf32f(vb.y);
            vb.z = f2tf32f(vb.z); vb.w = f2tf32f(vb.w);
            *(float4*)(&Bs[buf][k0r + r * 8][n4]) = vb;
        }
    };

    loadg(0); storeg(0); __syncthreads();
    int buf = 0;
    for (int k0 = 0; k0 < Cdim; k0 += BK) {
        bool more = (k0 + BK) < Cdim;
        if (more) loadg(k0 + BK);
        tile_mma(As[buf], Bs[buf], wm, wn, g, t, acc);
        if (more) storeg(buf ^ 1);
        __syncthreads();
        buf ^= 1;
    }

    float* Sb = g_S3 + (size_t)z * NN;
#pragma unroll
    for (int mi = 0; mi < 4; mi++)
#pragma unroll
        for (int r2 = 0; r2 < 2; r2++) {
            int y = y0 + wm + mi * 16 + g + r2 * 8;
#pragma unroll
            for (int ni = 0; ni < 4; ni++) {
                int zz = z0 + wn + ni * 8 + t * 2;
                size_t idx = (size_t)y * Ndim + zz;
                Sb[idx]     = acc[mi][ni][r2 * 2 + 0] * 0.0625f;
                Sb[idx + 1] = acc[mi][ni][r2 * 2 + 1] * 0.0625f;
            }
        }
}

// =====================================================================
// softmax, one block per row over all 3*4*2304 rows
// =====================================================================
__global__ void __launch_bounds__(256) softmax_kernel()
{
    const size_t row = blockIdx.x;
    float* p = g_S3 + row * Ndim;
    const int tid = threadIdx.x;
    const int warp = tid >> 5, lane = tid & 31;
    __shared__ float red[8];

    float v[9];
#pragma unroll
    for (int i = 0; i < 9; i++) v[i] = p[tid + i * 256];

    float mx = v[0];
#pragma unroll
    for (int i = 1; i < 9; i++) mx = fmaxf(mx, v[i]);
#pragma unroll
    for (int off = 16; off > 0; off >>= 1)
        mx = fmaxf(mx, __shfl_xor_sync(0xffffffffu, mx, off));
    if (lane == 0) red[warp] = mx;
    __syncthreads();
    if (warp == 0) {
        float m2 = red[lane & 7];
#pragma unroll
        for (int off = 4; off > 0; off >>= 1)
            m2 = fmaxf(m2, __shfl_xor_sync(0xffffffffu, m2, off));
        if (lane == 0) red[0] = m2;
    }
    __syncthreads();
    mx = red[0];

    float sum = 0.f;
#pragma unroll
    for (int i = 0; i < 9; i++) { v[i] = __expf(v[i] - mx); sum += v[i]; }
#pragma unroll
    for (int off = 16; off > 0; off >>= 1)
        sum += __shfl_xor_sync(0xffffffffu, sum, off);
    __syncthreads();
    if (lane == 0) red[warp] = sum;
    __syncthreads();
    if (warp == 0) {
        float s2 = red[lane & 7];
#pragma unroll
        for (int off = 4; off > 0; off >>= 1)
            s2 += __shfl_xor_sync(0xffffffffu, s2, off);
        if (lane == 0) red[0] = s2;
    }
    __syncthreads();
    const float inv = 1.f / red[0];
#pragma unroll
    for (int i = 0; i < 9; i++) p[tid + i * 256] = v[i] * inv;
}

// =====================================================================
// batched AV: z = attend*4 + b (grid z = 12)
// dst[c][n] = sum_m V[c][m] * P[n][m]
// =====================================================================
__global__ void __launch_bounds__(256, 2) av_mma3(Att3 A)
{
    __shared__ float As[2][BK][BMP];
    __shared__ float Bs[2][BK][BMP];
    const int z = blockIdx.z, a = z >> 2, b = z & 3;
    const int c0 = blockIdx.y * BM;
    const int n0 = blockIdx.x * BN;
    const int tid = threadIdx.x;
    const int warp = tid >> 5, lane = tid & 31;
    const int g = lane >> 2, t = lane & 3;
    const int wm = (warp & 1) * 64, wn = (warp >> 1) * 32;
    const float* Vb = A.V[a] + (size_t)b * CN;
    const float* Sb = g_S3 + (size_t)z * NN;
    float*      dst = A.O[a] + (size_t)b * CN;

    const int row = tid >> 1;
    const int kk0 = (tid & 1) * 8;

    DECL_ACC;

    float4 a_st[2], b_st[2];
    auto loadg = [&](int k0) {
#pragma unroll
        for (int r = 0; r < 2; r++) {
            a_st[r] = *(const float4*)(Vb + (size_t)(c0 + row) * Ndim + k0 + kk0 + r * 4);
            b_st[r] = *(const float4*)(Sb + (size_t)(n0 + row) * Ndim + k0 + kk0 + r * 4);
        }
    };
    auto storeg = [&](int buf) {
#pragma unroll
        for (int r = 0; r < 2; r++) {
            int kk = kk0 + r * 4;
            As[buf][kk + 0][row] = f2tf32f(a_st[r].x);
            As[buf][kk + 1][row] = f2tf32f(a_st[r].y);
            As[buf][kk + 2][row] = f2tf32f(a_st[r].z);
            As[buf][kk + 3][row] = f2tf32f(a_st[r].w);
            Bs[buf][kk + 0][row] = f2tf32f(b_st[r].x);
            Bs[buf][kk + 1][row] = f2tf32f(b_st[r].y);
            Bs[buf][kk + 2][row] = f2tf32f(b_st[r].z);
            Bs[buf][kk + 3][row] = f2tf32f(b_st[r].w);
        }
    };

    loadg(0); storeg(0); __syncthreads();
    int buf = 0;
    for (int k0 = 0; k0 < Ndim; k0 += BK) {
        bool more = (k0 + BK) < Ndim;
        if (more) loadg(k0 + BK);
        tile_mma(As[buf], Bs[buf], wm, wn, g, t, acc);
        if (more) storeg(buf ^ 1);
        __syncthreads();
        buf ^= 1;
    }

#pragma unroll
    for (int mi = 0; mi < 4; mi++)
#pragma unroll
        for (int r2 = 0; r2 < 2; r2++) {
            int c = c0 + wm + mi * 16 + g + r2 * 8;
#pragma unroll
            for (int ni = 0; ni < 4; ni++) {
                int n = n0 + wn + ni * 8 + t * 2;
                size_t idx = (size_t)c * Ndim + n;
                dst[idx]     = acc[mi][ni][r2 * 2 + 0];
                dst[idx + 1] = acc[mi][ni][r2 * 2 + 1];
            }
        }
}

// =====================================================================
// batched gate: z = m*4 + b (grid z=12); writes g_F3[m]
// =====================================================================
__global__ void __launch_bounds__(256, 2) gate_mma3(
    const float* __restrict__ Wg, const float* __restrict__ bg)
{
    __shared__ float As[2][BK][BMP];
    __shared__ float Bs[2][BK][BMP];
    const int z = blockIdx.z, a = z >> 2, b = z & 3;
    const int o0 = blockIdx.y * BM;
    const int n0 = blockIdx.x * BN;
    const int tid = threadIdx.x;
    const int warp = tid >> 5, lane = tid & 31;
    const int g = lane >> 2, t = lane & 3;
    const int wm = (warp & 1) * 64, wn = (warp >> 1) * 32;
    const float* Xb = g_W[a] + (size_t)b * CN;
    float*       F  = g_F3[a] + (size_t)b * CN;

    const int arow = tid >> 1;
    const int akk0 = (tid & 1) * 8;
    const int bn4 = (tid & 31) * 4;
    const int bk0 = tid >> 5;

    DECL_ACC;

    float4 a_st[2], b_st[2];
    auto loadg = [&](int k0) {
#pragma unroll
        for (int r = 0; r < 2; r++)
            a_st[r] = *(const float4*)(Wg + (size_t)(o0 + arow) * Cdim + k0 + akk0 + r * 4);
#pragma unroll
        for (int r = 0; r < 2; r++)
            b_st[r] = *(const float4*)(Xb + (size_t)(k0 + bk0 + r * 8) * Ndim + n0 + bn4);
    };
    auto storeg = [&](int buf) {
#pragma unroll
        for (int r = 0; r < 2; r++) {
            int kk = akk0 + r * 4;
            As[buf][kk + 0][arow] = f2tf32f(a_st[r].x);
            As[buf][kk + 1][arow] = f2tf32f(a_st[r].y);
            As[buf][kk + 2][arow] = f2tf32f(a_st[r].z);
            As[buf][kk + 3][arow] = f2tf32f(a_st[r].w);
        }
#pragma unroll
        for (int r = 0; r < 2; r++) {
            float4 v = b_st[r];
            v.x = f2tf32f(v.x); v.y = f2tf32f(v.y);
            v.z = f2tf32f(v.z); v.w = f2tf32f(v.w);
            *(float4*)(&Bs[buf][bk0 + r * 8][bn4]) = v;
        }
    };

    loadg(0); storeg(0); __syncthreads();
    int buf = 0;
    for (int k0 = 0; k0 < Cdim; k0 += BK) {
        bool more = (k0 + BK) < Cdim;
        if (more) loadg(k0 + BK);
        tile_mma(As[buf], Bs[buf], wm, wn, g, t, acc);
        if (more) storeg(buf ^ 1);
        __syncthreads();
        buf ^= 1;
    }

#pragma unroll
    for (int mi = 0; mi < 4; mi++)
#pragma unroll
        for (int r2 = 0; r2 < 2; r2++) {
            int o = o0 + wm + mi * 16 + g + r2 * 8;
            float bi = bg[o];
#pragma unroll
            for (int ni = 0; ni < 4; ni++) {
                int n = n0 + wn + ni * 8 + t * 2;
                size_t idx = (size_t)o * Ndim + n;
#pragma unroll
                for (int e = 0; e < 2; e++) {
                    float gv  = acc[mi][ni][r2 * 2 + e] + bi;
                    float sig = 1.f / (1.f + __expf(-gv));
                    F[idx + e] = sig * Xb[idx + e];
                }
            }
        }
}

// =====================================================================
// final conv: out = Wo @ (F0+F1+F2) + bo   (grid z = 4)
// =====================================================================
__global__ void __launch_bounds__(256, 2) final_mma(
    const float* __restrict__ Wo, const float* __restrict__ bo,
    float* __restrict__ out)
{
    __shared__ float As[2][BK][BMP];
    __shared__ float Bs[2][BK][BMP];
    const int b  = blockIdx.z;
    const int o0 = blockIdx.y * BM;
    const int n0 = blockIdx.x * BN;
    const int tid = threadIdx.x;
    const int warp = tid >> 5, lane = tid & 31;
    const int g = lane >> 2, t = lane & 3;
    const int wm = (warp & 1) * 64, wn = (warp >> 1) * 32;
    const float* F0 = g_F3[0] + (size_t)b * CN;
    const float* F1 = g_F3[1] + (size_t)b * CN;
    const float* F2 = g_F3[2] + (size_t)b * CN;
    float* dst = out + (size_t)b * CN;

    const int arow = tid >> 1;
    const int akk0 = (tid & 1) * 8;
    const int bn4 = (tid & 31) * 4;
    const int bk0 = tid >> 5;

    DECL_ACC;

    float4 a_st[2], b_st[2];
    auto loadg = [&](int k0) {
#pragma unroll
        for (int r = 0; r < 2; r++)
            a_st[r] = *(const float4*)(Wo + (size_t)(o0 + arow) * Cdim + k0 + akk0 + r * 4);
#pragma unroll
        for (int r = 0; r < 2; r++) {
            size_t off = (size_t)(k0 + bk0 + r * 8) * Ndim + n0 + bn4;
            float4 v0 = *(const float4*)(F0 + off);
            float4 v1 = *(const float4*)(F1 + off);
            float4 v2 = *(const float4*)(F2 + off);
            v0.x += v1.x + v2.x; v0.y += v1.y + v2.y;
            v0.z += v1.z + v2.z; v0.w += v1.w + v2.w;
            b_st[r] = v0;
        }
    };
    auto storeg = [&](int buf) {
#pragma unroll
        for (int r = 0; r < 2; r++) {
            int kk = akk0 + r * 4;
            As[buf][kk + 0][arow] = f2tf32f(a_st[r].x);
            As[buf][kk + 1][arow] = f2tf32f(a_st[r].y);
            As[buf][kk + 2][arow] = f2tf32f(a_st[r].z);
            As[buf][kk + 3][arow] = f2tf32f(a_st[r].w);
        }
#pragma unroll
        for (int r = 0; r < 2; r++) {
            float4 v = b_st[r];
            v.x = f2tf32f(v.x); v.y = f2tf32f(v.y);
            v.z = f2tf32f(v.z); v.w = f2tf32f(v.w);
            *(float4*)(&Bs[buf][bk0 + r * 8][bn4]) = v;
        }
    };

    loadg(0); storeg(0); __syncthreads();
    int buf = 0;
    for (int k0 = 0; k0 < Cdim; k0 += BK) {
        bool more = (k0 + BK) < Cdim;
        if (more) loadg(k0 + BK);
        tile_mma(As[buf], Bs[buf], wm, wn, g, t, acc);
        if (more) storeg(buf ^ 1);
        __syncthreads();
        buf ^= 1;
    }

#pragma unroll
    for (int mi = 0; mi < 4; mi++)
#pragma unroll
        for (int r2 = 0; r2 < 2; r2++) {
            int o = o0 + wm + mi * 16 + g + r2 * 8;
            float bi = bo[o];
#pragma unroll
            for (int ni = 0; ni < 4; ni++) {
                int n = n0 + wn + ni * 8 + t * 2;
                size_t idx = (size_t)o * Ndim + n;
                dst[idx]     = acc[mi][ni][r2 * 2 + 0] + bi;
                dst[idx + 1] = acc[mi][ni][r2 * 2 + 1] + bi;
            }
        }
}

// =====================================================================
// launch
// =====================================================================
extern "C" void kernel_launch(void* const* d_in, const int* in_sizes, int n_in,
                              void* d_out, int out_size)
{
    const float* x[3] = { (const float*)d_in[0], (const float*)d_in[1], (const float*)d_in[2] };
    const float* s = (const float*)d_in[3];
    const float *wq[3], *bq[3], *wk[3], *bk[3], *wv[3], *bv[3];
    for (int m = 0; m < 3; m++) {
        wq[m] = (const float*)d_in[4 + 6 * m];
        bq[m] = (const float*)d_in[5 + 6 * m];
        wk[m] = (const float*)d_in[6 + 6 * m];
        bk[m] = (const float*)d_in[7 + 6 * m];
        wv[m] = (const float*)d_in[8 + 6 * m];
        bv[m] = (const float*)d_in[9 + 6 * m];
    }
    const float* wg = (const float*)d_in[22];
    const float* bg = (const float*)d_in[23];
    const float* wo = (const float*)d_in[24];
    const float* bo = (const float*)d_in[25];
    float* out = (float*)d_out;

    float *gP, *gW;
    cudaGetSymbolAddress((void**)&gP, g_P);
    cudaGetSymbolAddress((void**)&gW, g_W);

    float* Q[3]; float* K[3]; float* V[3]; float* Wout[3];
    for (int m = 0; m < 3; m++) {
        Q[m]    = gP + (size_t)(0 + m) * PLANE;
        K[m]    = gP + (size_t)(3 + m) * PLANE;
        V[m]    = gP + (size_t)(6 + m) * PLANE;
        Wout[m] = gW + (size_t)m * PLANE;
    }

    Proj9 P;
    for (int m = 0; m < 3; m++) {
        P.X[3 * m + 0] = x[m]; P.W[3 * m + 0] = wq[m]; P.B[3 * m + 0] = bq[m];
        P.D[3 * m + 0] = Q[m]; P.sidx[3 * m + 0] = m;
        P.X[3 * m + 1] = x[m]; P.W[3 * m + 1] = wk[m]; P.B[3 * m + 1] = bk[m];
        P.D[3 * m + 1] = K[m]; P.sidx[3 * m + 1] = m;
        P.X[3 * m + 2] = x[m]; P.W[3 * m + 2] = wv[m]; P.B[3 * m + 2] = bv[m];
        P.D[3 * m + 2] = V[m]; P.sidx[3 * m + 2] = -1;
    }

    // attends: w_rgb(Q0; K2+K1; V0), w_depth(Q2; K0+K1; V2), w_thermal(Q1; K0+K2; V1)
    Att3 A;
    const int qi[3]  = { 0, 2, 1 };
    const int kai[3] = { 2, 0, 0 };
    const int kbi[3] = { 1, 1, 2 };
    for (int a = 0; a < 3; a++) {
        A.Q[a]  = Q[qi[a]];
        A.Ka[a] = K[kai[a]];
        A.Kb[a] = K[kbi[a]];
        A.V[a]  = V[qi[a]];
        A.O[a]  = Wout[a];
    }

    dim3 blk(256);
    proj_mma9 <<<dim3(Ndim / BN, Cdim / BM, 36), blk>>>(P, s);
    scores_mma3<<<dim3(Ndim / BN, Ndim / BM, 12), blk>>>(A);
    softmax_kernel<<<dim3(3 * Bdim * Ndim), blk>>>();
    av_mma3   <<<dim3(Ndim / BN, Cdim / BM, 12), blk>>>(A);
    gate_mma3 <<<dim3(Ndim / BN, Cdim / BM, 12), blk>>>(wg, bg);
    final_mma <<<dim3(Ndim / BN, Cdim / BM, 4), blk>>>(wo, bo, out);
}